// round 1
// baseline (speedup 1.0000x reference)
#include <cuda_runtime.h>
#include <cstdint>

// Problem shapes (fixed by the reference)
#define B_  512
#define C_  6
#define T_  77
#define D_  512
#define LI_ 193

// Output layout (floats), tuple order:
//   [0)                global_text  : B*D
//   [B*D)              global_image : B*D
//   [2*B*D)            local_text   : B*C*D
//   [2*B*D + B*C*D)    logit_scale  : 1
#define OFF_GT 0
#define OFF_GI (B_ * D_)
#define OFF_LT (2 * B_ * D_)
#define OFF_LS (2 * B_ * D_ + B_ * C_ * D_)

// One CTA per batch. 128 threads; each thread owns 4 contiguous d's (float4).
__global__ __launch_bounds__(128, 8)
void clip_fused_kernel(const float* __restrict__ image_features,   // [B, LI, D]
                       const float* __restrict__ text_features,    // [B, T, D]
                       const float* __restrict__ logit_scale,      // [1]
                       const int*   __restrict__ captions,         // [B, T]
                       const int*   __restrict__ noun_chunk_mask,  // [B, C, T]
                       float* __restrict__ out)
{
    const int b   = blockIdx.x;
    const int tid = threadIdx.x;

    __shared__ int     s_mask[T_];   // packed: bit c set if mask[b,c,t] != 0
    __shared__ int     s_val[128];
    __shared__ int     s_idx[128];

    // ---- Stage packed noun_chunk_mask and captions value for argmax ----
    if (tid < T_) {
        int pack = 0;
        const int* mrow = noun_chunk_mask + (size_t)b * C_ * T_ + tid;
        #pragma unroll
        for (int c = 0; c < C_; ++c) {
            if (mrow[c * T_] != 0) pack |= (1 << c);
        }
        s_mask[tid] = pack;
        s_val[tid]  = captions[(size_t)b * T_ + tid];
        s_idx[tid]  = tid;
    } else {
        s_val[tid] = INT32_MIN;
        s_idx[tid] = T_;  // never wins
    }
    __syncthreads();

    // ---- Argmax reduce (first occurrence on ties) ----
    #pragma unroll
    for (int s = 64; s > 0; s >>= 1) {
        if (tid < s) {
            int v2 = s_val[tid + s], i2 = s_idx[tid + s];
            int v1 = s_val[tid],     i1 = s_idx[tid];
            if (v2 > v1 || (v2 == v1 && i2 < i1)) {
                s_val[tid] = v2;
                s_idx[tid] = i2;
            }
        }
        __syncthreads();
    }
    const int eot = s_idx[0];

    // ---- Stream text_features[b] once; accumulate 6 masked sums ----
    const float4* trow = reinterpret_cast<const float4*>(
        text_features + (size_t)b * T_ * D_) + tid;  // [T][D/4], thread owns column tid

    float4 acc[C_];
    #pragma unroll
    for (int c = 0; c < C_; ++c) acc[c] = make_float4(0.f, 0.f, 0.f, 0.f);

    float4 gtext = make_float4(0.f, 0.f, 0.f, 0.f);

    #pragma unroll 7
    for (int t = 0; t < T_; ++t) {
        float4 x = trow[t * (D_ / 4)];
        int pack = s_mask[t];
        #pragma unroll
        for (int c = 0; c < C_; ++c) {
            if (pack & (1 << c)) {
                acc[c].x += x.x; acc[c].y += x.y;
                acc[c].z += x.z; acc[c].w += x.w;
            }
        }
        if (t == eot) gtext = x;
    }

    const float inv_T = 1.0f / (float)T_;

    // local_text [B, C, D]
    float4* lt = reinterpret_cast<float4*>(out + OFF_LT + (size_t)b * C_ * D_) + tid;
    #pragma unroll
    for (int c = 0; c < C_; ++c) {
        float4 r;
        r.x = acc[c].x * inv_T; r.y = acc[c].y * inv_T;
        r.z = acc[c].z * inv_T; r.w = acc[c].w * inv_T;
        lt[c * (D_ / 4)] = r;
    }

    // global_text [B, D]
    reinterpret_cast<float4*>(out + OFF_GT + (size_t)b * D_)[tid] = gtext;

    // global_image [B, D] = image_features[b, 0, :]
    float4 gi = reinterpret_cast<const float4*>(
        image_features + (size_t)b * LI_ * D_)[tid];
    reinterpret_cast<float4*>(out + OFF_GI + (size_t)b * D_)[tid] = gi;

    // logit_scale passthrough (single thread once)
    if (b == 0 && tid == 0) {
        out[OFF_LS] = logit_scale[0];
    }
}

extern "C" void kernel_launch(void* const* d_in, const int* in_sizes, int n_in,
                              void* d_out, int out_size)
{
    const float* image_features  = (const float*)d_in[0];
    const float* text_features   = (const float*)d_in[1];
    const float* logit_scale     = (const float*)d_in[2];
    const int*   captions        = (const int*)d_in[3];
    const int*   noun_chunk_mask = (const int*)d_in[4];
    float* out = (float*)d_out;

    clip_fused_kernel<<<B_, 128>>>(image_features, text_features, logit_scale,
                                   captions, noun_chunk_mask, out);
}

// round 2
// speedup vs baseline: 1.1098x; 1.1098x over previous
#include <cuda_runtime.h>
#include <cstdint>

// Problem shapes (fixed by the reference)
#define B_  512
#define C_  6
#define T_  77
#define D_  512
#define LI_ 193

// Output layout (floats), tuple order:
//   [0)                global_text  : B*D
//   [B*D)              global_image : B*D
//   [2*B*D)            local_text   : B*C*D
//   [2*B*D + B*C*D)    logit_scale  : 1
#define OFF_GT 0
#define OFF_GI (B_ * D_)
#define OFF_LT (2 * B_ * D_)
#define OFF_LS (2 * B_ * D_ + B_ * C_ * D_)

#define T_SPLIT 39   // half 0: t in [0,39), half 1: t in [39,77)

// One CTA per batch. 256 threads in two halves of the T range;
// each thread owns 4 contiguous d's (float4 column col = tid & 127).
__global__ __launch_bounds__(256, 4)
void clip_fused_kernel(const float* __restrict__ image_features,   // [B, LI, D]
                       const float* __restrict__ text_features,    // [B, T, D]
                       const float* __restrict__ logit_scale,      // [1]
                       const int*   __restrict__ captions,         // [B, T]
                       const int*   __restrict__ noun_chunk_mask,  // [B, C, T]
                       float* __restrict__ out)
{
    const int b    = blockIdx.x;
    const int tid  = threadIdx.x;
    const int half = tid >> 7;      // 0 or 1
    const int col  = tid & 127;     // float4 column within D

    __shared__ int    s_mask[T_];           // packed: bit c set if mask[b,c,t] != 0
    __shared__ int    s_val[128];
    __shared__ int    s_idx[128];
    __shared__ float4 s_acc[2][C_][128];    // partial sums per half

    // ---- Stage packed noun_chunk_mask and caption values for argmax ----
    if (tid < T_) {
        int pack = 0;
        const int* mrow = noun_chunk_mask + (size_t)b * C_ * T_ + tid;
        #pragma unroll
        for (int c = 0; c < C_; ++c) {
            if (mrow[c * T_] != 0) pack |= (1 << c);
        }
        s_mask[tid] = pack;
        s_val[tid]  = captions[(size_t)b * T_ + tid];
        s_idx[tid]  = tid;
    } else if (tid < 128) {
        s_val[tid] = INT32_MIN;
        s_idx[tid] = T_;  // never wins
    }
    __syncthreads();

    // ---- Argmax reduce on first 128 threads (first occurrence on ties) ----
    #pragma unroll
    for (int s = 64; s > 0; s >>= 1) {
        if (tid < s) {
            int v2 = s_val[tid + s], i2 = s_idx[tid + s];
            int v1 = s_val[tid],     i1 = s_idx[tid];
            if (v2 > v1 || (v2 == v1 && i2 < i1)) {
                s_val[tid] = v2;
                s_idx[tid] = i2;
            }
        }
        __syncthreads();
    }
    const int eot = s_idx[0];

    // ---- Stream this half's T range once; accumulate 6 masked partial sums ----
    const int t0 = half ? T_SPLIT : 0;
    const int t1 = half ? T_      : T_SPLIT;

    const float4* trow = reinterpret_cast<const float4*>(
        text_features + (size_t)b * T_ * D_) + col;  // [T][D/4]

    float4 acc[C_];
    #pragma unroll
    for (int c = 0; c < C_; ++c) acc[c] = make_float4(0.f, 0.f, 0.f, 0.f);

    float4 gtext = make_float4(0.f, 0.f, 0.f, 0.f);
    const bool hasEot = (eot >= t0) && (eot < t1);

    #pragma unroll 4
    for (int t = t0; t < t1; ++t) {
        float4 x = trow[t * (D_ / 4)];
        int pack = s_mask[t];
        #pragma unroll
        for (int c = 0; c < C_; ++c) {
            if (pack & (1 << c)) {
                acc[c].x += x.x; acc[c].y += x.y;
                acc[c].z += x.z; acc[c].w += x.w;
            }
        }
        if (t == eot) gtext = x;
    }

    // global_text [B, D] — only the half containing eot has the row
    if (hasEot) {
        reinterpret_cast<float4*>(out + OFF_GT + (size_t)b * D_)[col] = gtext;
    }

    // global_image [B, D] = image_features[b, 0, :] — half 1 handles it
    if (half) {
        float4 gi = reinterpret_cast<const float4*>(
            image_features + (size_t)b * LI_ * D_)[col];
        reinterpret_cast<float4*>(out + OFF_GI + (size_t)b * D_)[col] = gi;
    }

    // ---- Exchange partials through smem; each half finalizes 3 channels ----
    #pragma unroll
    for (int c = 0; c < C_; ++c) s_acc[half][c][col] = acc[c];
    __syncthreads();

    const float inv_T = 1.0f / (float)T_;
    float4* lt = reinterpret_cast<float4*>(out + OFF_LT + (size_t)b * C_ * D_) + col;

    const int c0 = half * (C_ / 2);
    #pragma unroll
    for (int k = 0; k < C_ / 2; ++k) {
        const int c = c0 + k;
        float4 a0 = s_acc[0][c][col];
        float4 a1 = s_acc[1][c][col];
        float4 r;
        r.x = (a0.x + a1.x) * inv_T;
        r.y = (a0.y + a1.y) * inv_T;
        r.z = (a0.z + a1.z) * inv_T;
        r.w = (a0.w + a1.w) * inv_T;
        lt[c * (D_ / 4)] = r;
    }

    // logit_scale passthrough (single thread once)
    if (b == 0 && tid == 0) {
        out[OFF_LS] = logit_scale[0];
    }
}

extern "C" void kernel_launch(void* const* d_in, const int* in_sizes, int n_in,
                              void* d_out, int out_size)
{
    const float* image_features  = (const float*)d_in[0];
    const float* text_features   = (const float*)d_in[1];
    const float* logit_scale     = (const float*)d_in[2];
    const int*   captions        = (const int*)d_in[3];
    const int*   noun_chunk_mask = (const int*)d_in[4];
    float* out = (float*)d_out;

    clip_fused_kernel<<<B_, 256>>>(image_features, text_features, logit_scale,
                                   captions, noun_chunk_mask, out);
}